// round 3
// baseline (speedup 1.0000x reference)
#include <cuda_runtime.h>
#include <cuda_bf16.h>

#define EPSV 1e-8f

__global__ void __launch_bounds__(256)
cov3d_kernel(const float4* __restrict__ quat,   // N x 4
             const float*  __restrict__ scale,  // N x 3
             float* __restrict__ out,           // N x 9
             int n)
{
    int i = blockIdx.x * blockDim.x + threadIdx.x;
    int stride = gridDim.x * blockDim.x;
    for (; i < n; i += stride) {
        // ---- load quaternion (vectorized, streaming) ----
        float4 q = __ldcs(quat + i);
        float w = q.x, x = q.y, y = q.z, z = q.w;

        // ---- load scale (streaming) ----
        const float* sp = scale + 3 * i;
        float s0 = fabsf(__ldcs(sp + 0)) + EPSV;
        float s1 = fabsf(__ldcs(sp + 1)) + EPSV;
        float s2 = fabsf(__ldcs(sp + 2)) + EPSV;
        float s0sq = s0 * s0, s1sq = s1 * s1, s2sq = s2 * s2;

        // ---- rotation matrix with 1/||q||^2 folded in ----
        // All entries of R are quadratic in the normalized quaternion, so
        // R(q/||q||) = Rraw(q) / (q . q).
        float nrm2 = w*w + x*x + y*y + z*z;
        float inv = 1.0f / nrm2;

        float xx = x*x, yy = y*y, zz = z*z;
        float xy = x*y, xz = x*z, yz = y*z;
        float wx = w*x, wy = w*y, wz = w*z;
        float ww = w*w;

        // Row-major R; columns c_j are scaled by s_j.
        // r[i][j]
        float r00 = (ww + xx - yy - zz) * inv;        // 1-2(y^2+z^2) normalized
        float r01 = 2.0f * (xy - wz) * inv;
        float r02 = 2.0f * (xz + wy) * inv;
        float r10 = 2.0f * (xy + wz) * inv;
        float r11 = (ww - xx + yy - zz) * inv;
        float r12 = 2.0f * (yz - wx) * inv;
        float r20 = 2.0f * (xz - wy) * inv;
        float r21 = 2.0f * (yz + wx) * inv;
        float r22 = (ww - xx - yy + zz) * inv;

        // ---- M = R diag(s^2) R^T  (symmetric) ----
        float m00 = s0sq*r00*r00 + s1sq*r01*r01 + s2sq*r02*r02;
        float m01 = s0sq*r00*r10 + s1sq*r01*r11 + s2sq*r02*r12;
        float m02 = s0sq*r00*r20 + s1sq*r01*r21 + s2sq*r02*r22;
        float m11 = s0sq*r10*r10 + s1sq*r11*r11 + s2sq*r12*r12;
        float m12 = s0sq*r10*r20 + s1sq*r11*r21 + s2sq*r12*r22;
        float m22 = s0sq*r20*r20 + s1sq*r21*r21 + s2sq*r22*r22;

        // ---- store 9 floats, streaming (no reuse) ----
        float* op = out + 9 * i;
        __stcs(op + 0, m00);
        __stcs(op + 1, m01);
        __stcs(op + 2, m02);
        __stcs(op + 3, m01);
        __stcs(op + 4, m11);
        __stcs(op + 5, m12);
        __stcs(op + 6, m02);
        __stcs(op + 7, m12);
        __stcs(op + 8, m22);
    }
}

extern "C" void kernel_launch(void* const* d_in, const int* in_sizes, int n_in,
                              void* d_out, int out_size)
{
    const float4* quat  = (const float4*)d_in[0];  // N x 4 float32
    const float*  scale = (const float*) d_in[1];  // N x 3 float32
    float* out = (float*)d_out;                    // N x 3 x 3 float32

    int n = in_sizes[0] / 4;
    int threads = 256;
    int blocks = (n + threads - 1) / threads;
    // Cap the grid modestly above the wave count; grid-stride handles the rest.
    if (blocks > 148 * 32) blocks = 148 * 32;
    cov3d_kernel<<<blocks, threads>>>(quat, scale, out, n);
}

// round 4
// speedup vs baseline: 2.7081x; 2.7081x over previous
#include <cuda_runtime.h>
#include <cuda_bf16.h>

#define EPSV 1e-8f
#define TPB 256

__global__ void __launch_bounds__(TPB)
cov3d_kernel(const float4* __restrict__ quat,   // N x 4
             const float*  __restrict__ scale,  // N x 3
             float* __restrict__ out,           // N x 9
             int n)
{
    __shared__ float s_scale[TPB * 3];
    __shared__ __align__(16) float s_out[TPB * 9];

    const int tile_base = blockIdx.x * TPB;      // first element of this tile
    const int remain = min(TPB, n - tile_base);  // elements in this tile

    // ---- stage scale: coalesced contiguous loads into smem ----
    {
        const int gbase = tile_base * 3;
        const int count = remain * 3;
        #pragma unroll
        for (int j = threadIdx.x; j < TPB * 3; j += TPB) {
            s_scale[j] = (j < count) ? __ldcs(scale + gbase + j) : 1.0f;
        }
    }
    __syncthreads();

    // ---- compute one Gaussian per thread ----
    const int i = tile_base + threadIdx.x;
    if (threadIdx.x < remain) {
        float4 q = __ldcs(quat + i);
        float w = q.x, x = q.y, y = q.z, z = q.w;

        // scale from smem (stride 3, conflict-free: gcd(3,32)=1)
        float s0 = fabsf(s_scale[threadIdx.x * 3 + 0]) + EPSV;
        float s1 = fabsf(s_scale[threadIdx.x * 3 + 1]) + EPSV;
        float s2 = fabsf(s_scale[threadIdx.x * 3 + 2]) + EPSV;
        float s0sq = s0 * s0, s1sq = s1 * s1, s2sq = s2 * s2;

        // Rotation with 1/||q||^2 folded in (R entries quadratic in q).
        float nrm2 = w*w + x*x + y*y + z*z;
        float inv = 1.0f / nrm2;

        float xx = x*x, yy = y*y, zz = z*z;
        float xy = x*y, xz = x*z, yz = y*z;
        float wx = w*x, wy = w*y, wz = w*z;
        float ww = w*w;

        float r00 = (ww + xx - yy - zz) * inv;
        float r01 = 2.0f * (xy - wz) * inv;
        float r02 = 2.0f * (xz + wy) * inv;
        float r10 = 2.0f * (xy + wz) * inv;
        float r11 = (ww - xx + yy - zz) * inv;
        float r12 = 2.0f * (yz - wx) * inv;
        float r20 = 2.0f * (xz - wy) * inv;
        float r21 = 2.0f * (yz + wx) * inv;
        float r22 = (ww - xx - yy + zz) * inv;

        // M = R diag(s^2) R^T (symmetric)
        float m00 = s0sq*r00*r00 + s1sq*r01*r01 + s2sq*r02*r02;
        float m01 = s0sq*r00*r10 + s1sq*r01*r11 + s2sq*r02*r12;
        float m02 = s0sq*r00*r20 + s1sq*r01*r21 + s2sq*r02*r22;
        float m11 = s0sq*r10*r10 + s1sq*r11*r11 + s2sq*r12*r12;
        float m12 = s0sq*r10*r20 + s1sq*r11*r21 + s2sq*r12*r22;
        float m22 = s0sq*r20*r20 + s1sq*r21*r21 + s2sq*r22*r22;

        // stage into smem at stride 9 (gcd(9,32)=1 -> conflict-free)
        float* o = s_out + threadIdx.x * 9;
        o[0] = m00; o[1] = m01; o[2] = m02;
        o[3] = m01; o[4] = m11; o[5] = m12;
        o[6] = m02; o[7] = m12; o[8] = m22;
    }
    __syncthreads();

    // ---- flush to global: coalesced float4 streaming stores ----
    if (remain == TPB) {
        // full tile: 256*9 floats = 576 float4, 16B-aligned (tile_base%256==0)
        float4* o4 = (float4*)(out + (size_t)tile_base * 9);
        const float4* s4 = (const float4*)s_out;
        #pragma unroll
        for (int j = threadIdx.x; j < TPB * 9 / 4; j += TPB) {
            __stcs(o4 + j, s4[j]);
        }
    } else {
        float* og = out + (size_t)tile_base * 9;
        for (int j = threadIdx.x; j < remain * 9; j += TPB) {
            __stcs(og + j, s_out[j]);
        }
    }
}

extern "C" void kernel_launch(void* const* d_in, const int* in_sizes, int n_in,
                              void* d_out, int out_size)
{
    const float4* quat  = (const float4*)d_in[0];  // N x 4 float32
    const float*  scale = (const float*) d_in[1];  // N x 3 float32
    float* out = (float*)d_out;                    // N x 3 x 3 float32

    int n = in_sizes[0] / 4;
    int tiles = (n + TPB - 1) / TPB;
    cov3d_kernel<<<tiles, TPB>>>(quat, scale, out, n);
}

// round 6
// speedup vs baseline: 2.9479x; 1.0885x over previous
#include <cuda_runtime.h>
#include <cuda_bf16.h>

#define EPSV 1e-8f
#define TPB 256
#define WARPS 8
#define EPT 4                    // elements per thread
#define WELEMS (32 * EPT)        // 128 elements per warp tile

__global__ void __launch_bounds__(TPB)
cov3d_kernel(const float4* __restrict__ quat,   // N x 4
             const float*  __restrict__ scale,  // N x 3
             float* __restrict__ out,           // N x 9
             int n)
{
    // One private region per warp: 128 elems * 9 floats = 1152 floats (4608 B).
    // Reused: first 384 floats hold staged scale, then overwritten by outputs.
    __shared__ __align__(16) float s_buf[WARPS][WELEMS * 9];

    const int warp = threadIdx.x >> 5;
    const int lane = threadIdx.x & 31;

    const int base = (blockIdx.x * WARPS + warp) * WELEMS;  // warp's first element
    if (base < n) {                                          // warp-uniform guard
        const int wrem = min(WELEMS, n - base);
        float* buf = s_buf[warp];

        // ---- batch quaternion loads first (4 independent LDG.128 in flight) ----
        float4 q[EPT];
        #pragma unroll
        for (int e = 0; e < EPT; e++) {
            int li = e * 32 + lane;
            if (li < wrem) q[e] = __ldcs(quat + base + li);
        }

        // ---- stage scale coalesced into smem (3 more LDG.128 in flight) ----
        if (wrem == WELEMS) {
            const float4* sp4 = (const float4*)(scale + (size_t)base * 3);
            float4* b4 = (float4*)buf;
            #pragma unroll
            for (int k = 0; k < 3; k++)
                b4[lane + k * 32] = __ldcs(sp4 + lane + k * 32);
        } else {
            const float* sp = scale + (size_t)base * 3;
            for (int j = lane; j < wrem * 3; j += 32)
                buf[j] = __ldcs(sp + j);
        }
        __syncwarp();

        // ---- read per-element scales (stride-3 smem: conflict-free) ----
        float sc[EPT][3];
        #pragma unroll
        for (int e = 0; e < EPT; e++) {
            int li = e * 32 + lane;
            if (li < wrem) {
                sc[e][0] = buf[li * 3 + 0];
                sc[e][1] = buf[li * 3 + 1];
                sc[e][2] = buf[li * 3 + 2];
            }
        }
        __syncwarp();   // scale reads done before buf is reused for outputs

        // ---- compute + stage outputs (stride-9 smem writes: conflict-free) ----
        #pragma unroll
        for (int e = 0; e < EPT; e++) {
            int li = e * 32 + lane;
            if (li >= wrem) continue;

            float w = q[e].x, x = q[e].y, y = q[e].z, z = q[e].w;

            float s0 = fabsf(sc[e][0]) + EPSV;
            float s1 = fabsf(sc[e][1]) + EPSV;
            float s2 = fabsf(sc[e][2]) + EPSV;
            float s0sq = s0 * s0, s1sq = s1 * s1, s2sq = s2 * s2;

            // Rotation with 1/||q||^2 folded in (R entries quadratic in q).
            float ww = w * w, xx = x * x, yy = y * y, zz = z * z;
            float inv = 1.0f / (ww + xx + yy + zz);
            float xy = x * y, xz = x * z, yz = y * z;
            float wx = w * x, wy = w * y, wz = w * z;

            float r00 = (ww + xx - yy - zz) * inv;
            float r01 = 2.0f * (xy - wz) * inv;
            float r02 = 2.0f * (xz + wy) * inv;
            float r10 = 2.0f * (xy + wz) * inv;
            float r11 = (ww - xx + yy - zz) * inv;
            float r12 = 2.0f * (yz - wx) * inv;
            float r20 = 2.0f * (xz - wy) * inv;
            float r21 = 2.0f * (yz + wx) * inv;
            float r22 = (ww - xx - yy + zz) * inv;

            // M = R diag(s^2) R^T (symmetric)
            float m00 = s0sq*r00*r00 + s1sq*r01*r01 + s2sq*r02*r02;
            float m01 = s0sq*r00*r10 + s1sq*r01*r11 + s2sq*r02*r12;
            float m02 = s0sq*r00*r20 + s1sq*r01*r21 + s2sq*r02*r22;
            float m11 = s0sq*r10*r10 + s1sq*r11*r11 + s2sq*r12*r12;
            float m12 = s0sq*r10*r20 + s1sq*r11*r21 + s2sq*r12*r22;
            float m22 = s0sq*r20*r20 + s1sq*r21*r21 + s2sq*r22*r22;

            float* o = buf + li * 9;
            o[0] = m00; o[1] = m01; o[2] = m02;
            o[3] = m01; o[4] = m11; o[5] = m12;
            o[6] = m02; o[7] = m12; o[8] = m22;
        }
        __syncwarp();

        // ---- flush: coalesced float4 streaming stores (min wavefronts) ----
        if (wrem == WELEMS) {
            float4* o4 = (float4*)(out + (size_t)base * 9);
            const float4* b4 = (const float4*)buf;
            #pragma unroll
            for (int k = 0; k < 9; k++)
                __stcs(o4 + lane + k * 32, b4[lane + k * 32]);
        } else {
            float* og = out + (size_t)base * 9;
            for (int j = lane; j < wrem * 9; j += 32)
                __stcs(og + j, buf[j]);
        }
    }
}

extern "C" void kernel_launch(void* const* d_in, const int* in_sizes, int n_in,
                              void* d_out, int out_size)
{
    const float4* quat  = (const float4*)d_in[0];  // N x 4 float32
    const float*  scale = (const float*) d_in[1];  // N x 3 float32
    float* out = (float*)d_out;                    // N x 3 x 3 float32

    int n = in_sizes[0] / 4;
    int elems_per_block = TPB * EPT;               // 1024
    int blocks = (n + elems_per_block - 1) / elems_per_block;
    cov3d_kernel<<<blocks, TPB>>>(quat, scale, out, n);
}